// round 2
// baseline (speedup 1.0000x reference)
#include <cuda_runtime.h>
#include <cuda_bf16.h>
#include <math.h>

// Problem constants
#define B_  2
#define T_  1024
#define C_  2048
#define NH  16      // query heads
#define KH  4       // kv heads
#define G_  4       // NH / KH
#define H_  128     // head dim
#define M_  (B_*T_) // 2048 rows

// Scratch (static device globals — allocation-free)
__device__ float g_q[M_ * C_];        // 16 MB  [B*T, N*H]
__device__ float g_k[M_ * (KH*H_)];   // 4 MB   [B*T, K*H]
__device__ float g_v[M_ * (KH*H_)];   // 4 MB
__device__ float g_enc[M_ * C_];      // 16 MB

// ---------------------------------------------------------------------------
// Tiled fp32 SGEMM: C[M,N] = A[M,K] @ B[K,N]. Requires M%64==0, N%64==0, K%16==0.
// 64x64 block tile, BK=16, 256 threads, 4x4 per thread.
// ---------------------------------------------------------------------------
__global__ void sgemm64(const float* __restrict__ A, const float* __restrict__ B,
                        float* __restrict__ C, int M, int N, int K) {
    __shared__ float As[16][64];
    __shared__ float Bs[16][64];

    const int tid = threadIdx.x;
    const int tx = tid & 15;
    const int ty = tid >> 4;
    const int bm0 = blockIdx.y * 64;
    const int bn0 = blockIdx.x * 64;

    const int a_r = tid >> 2;          // 0..63
    const int a_c = (tid & 3) << 2;    // 0,4,8,12
    const int b_r = tid >> 4;          // 0..15
    const int b_c = (tid & 15) << 2;   // 0..60

    float acc[4][4];
    #pragma unroll
    for (int u = 0; u < 4; u++)
        #pragma unroll
        for (int v = 0; v < 4; v++) acc[u][v] = 0.f;

    for (int k0 = 0; k0 < K; k0 += 16) {
        float4 av = *(const float4*)&A[(size_t)(bm0 + a_r) * K + k0 + a_c];
        float4 bv = *(const float4*)&B[(size_t)(k0 + b_r) * N + bn0 + b_c];
        As[a_c + 0][a_r] = av.x;
        As[a_c + 1][a_r] = av.y;
        As[a_c + 2][a_r] = av.z;
        As[a_c + 3][a_r] = av.w;
        *(float4*)&Bs[b_r][b_c] = bv;
        __syncthreads();

        #pragma unroll
        for (int kk = 0; kk < 16; kk++) {
            float a[4], b[4];
            #pragma unroll
            for (int u = 0; u < 4; u++) a[u] = As[kk][ty * 4 + u];
            #pragma unroll
            for (int v = 0; v < 4; v++) b[v] = Bs[kk][tx * 4 + v];
            #pragma unroll
            for (int u = 0; u < 4; u++)
                #pragma unroll
                for (int v = 0; v < 4; v++)
                    acc[u][v] = fmaf(a[u], b[v], acc[u][v]);
        }
        __syncthreads();
    }

    #pragma unroll
    for (int u = 0; u < 4; u++) {
        float4 o = make_float4(acc[u][0], acc[u][1], acc[u][2], acc[u][3]);
        *(float4*)&C[(size_t)(bm0 + ty * 4 + u) * N + bn0 + tx * 4] = o;
    }
}

// ---------------------------------------------------------------------------
// Fused RMSNorm (over full row of width D) + RoPE (per 128-wide head) + scale.
// In-place on buf. One block (256 threads) per row. t = row % T_.
// ---------------------------------------------------------------------------
__global__ void rmsrope_kernel(float* __restrict__ buf, int D, float scale) {
    __shared__ float s_x[2048];
    __shared__ float s_wred[8];

    const int row = blockIdx.x;
    const int t = row % T_;
    const int tid = threadIdx.x;
    const int lane = tid & 31;
    const int warp = tid >> 5;
    float* rp = buf + (size_t)row * D;

    float ss = 0.f;
    for (int d = tid; d < D; d += 256) {
        float v = rp[d];
        s_x[d] = v;
        ss = fmaf(v, v, ss);
    }
    #pragma unroll
    for (int off = 16; off > 0; off >>= 1)
        ss += __shfl_xor_sync(0xffffffffu, ss, off);
    if (lane == 0) s_wred[warp] = ss;
    __syncthreads();
    float tot = 0.f;
    #pragma unroll
    for (int w = 0; w < 8; w++) tot += s_wred[w];
    const float inv = rsqrtf(tot / (float)D + 1e-6f) * scale;

    for (int d = tid; d < D; d += 256) {
        int h = d & 127;         // position within head
        int i = h & 63;          // frequency index
        float fraction = (float)i * (1.0f / 64.0f);
        float inv_freq = powf(10000.0f, -fraction);
        float ang = (float)t * inv_freq;
        float sv = sinf(ang), cv = cosf(ang);
        float xn = s_x[d] * inv;
        float partner = (h < 64) ? s_x[d + 64] : s_x[d - 64];
        partner *= inv;
        float val = (h < 64) ? fmaf(xn, cv, -partner * sv)
                             : fmaf(xn, cv,  partner * sv);
        rp[d] = val;
    }
}

// ---------------------------------------------------------------------------
// Attention: one block = 8 queries (one warp each) for one (b, head n).
// Full (non-causal) softmax over s=0..1023, 32-key tiles in smem, online softmax.
// q is pre-scaled by 1/sqrt(H).
// ---------------------------------------------------------------------------
#define ST 32
__global__ void attn_kernel(const float* __restrict__ q, const float* __restrict__ k,
                            const float* __restrict__ v, float* __restrict__ enc) {
    __shared__ float q_s[8][128];
    __shared__ float k_s[ST][129];
    __shared__ float v_s[ST][129];

    const int tid = threadIdx.x;
    const int lane = tid & 31;
    const int warp = tid >> 5;
    const int b = blockIdx.z;
    const int n = blockIdx.y;
    const int kh = n >> 2;             // n / G
    const int t0 = blockIdx.x * 8;
    const int t = t0 + warp;

    // load 8x128 q tile (one float4 per thread)
    {
        int qrow = tid >> 5;
        int qc = (tid & 31) << 2;
        float4 qv = *(const float4*)&q[((size_t)(b * T_ + t0 + qrow) * C_) + n * H_ + qc];
        *(float4*)&q_s[qrow][qc] = qv;
    }

    float m = -INFINITY, l = 0.f;
    float o0 = 0.f, o1 = 0.f, o2 = 0.f, o3 = 0.f;

    for (int s0 = 0; s0 < T_; s0 += ST) {
        __syncthreads();
        // load k/v 32x128 tiles (4 float4 per thread each)
        #pragma unroll
        for (int j = 0; j < 4; j++) {
            int i = tid + j * 256;
            int srow = i >> 5;
            int c4 = (i & 31) << 2;
            size_t goff = ((size_t)(b * T_ + s0 + srow) * (KH * H_)) + kh * H_ + c4;
            float4 kv = *(const float4*)&k[goff];
            float4 vv = *(const float4*)&v[goff];
            k_s[srow][c4 + 0] = kv.x; k_s[srow][c4 + 1] = kv.y;
            k_s[srow][c4 + 2] = kv.z; k_s[srow][c4 + 3] = kv.w;
            v_s[srow][c4 + 0] = vv.x; v_s[srow][c4 + 1] = vv.y;
            v_s[srow][c4 + 2] = vv.z; v_s[srow][c4 + 3] = vv.w;
        }
        __syncthreads();

        // logit for s = s0 + lane
        float lg = 0.f;
        #pragma unroll 8
        for (int h = 0; h < 128; h++)
            lg = fmaf(q_s[warp][h], k_s[lane][h], lg);

        // warp max
        float mx = lg;
        #pragma unroll
        for (int off = 16; off > 0; off >>= 1)
            mx = fmaxf(mx, __shfl_xor_sync(0xffffffffu, mx, off));
        float m_new = fmaxf(m, mx);
        float alpha = expf(m - m_new);
        float p = expf(lg - m_new);
        float ps = p;
        #pragma unroll
        for (int off = 16; off > 0; off >>= 1)
            ps += __shfl_xor_sync(0xffffffffu, ps, off);
        l = l * alpha + ps;
        o0 *= alpha; o1 *= alpha; o2 *= alpha; o3 *= alpha;
        m = m_new;

        #pragma unroll
        for (int sl = 0; sl < ST; sl++) {
            float pb = __shfl_sync(0xffffffffu, p, sl);
            o0 = fmaf(pb, v_s[sl][lane],       o0);
            o1 = fmaf(pb, v_s[sl][32 + lane],  o1);
            o2 = fmaf(pb, v_s[sl][64 + lane],  o2);
            o3 = fmaf(pb, v_s[sl][96 + lane],  o3);
        }
    }

    float il = 1.0f / l;
    size_t ob = ((size_t)(b * T_ + t) * C_) + n * H_;
    enc[ob + lane]       = o0 * il;
    enc[ob + 32 + lane]  = o1 * il;
    enc[ob + 64 + lane]  = o2 * il;
    enc[ob + 96 + lane]  = o3 * il;
}

// ---------------------------------------------------------------------------
extern "C" void kernel_launch(void* const* d_in, const int* in_sizes, int n_in,
                              void* d_out, int out_size) {
    const float* x  = (const float*)d_in[0];
    const float* wq = (const float*)d_in[1];
    const float* wk = (const float*)d_in[2];
    const float* wv = (const float*)d_in[3];
    const float* wo = (const float*)d_in[4];
    float* out = (float*)d_out;

    float *gq, *gk, *gv, *genc;
    cudaGetSymbolAddress((void**)&gq, g_q);
    cudaGetSymbolAddress((void**)&gk, g_k);
    cudaGetSymbolAddress((void**)&gv, g_v);
    cudaGetSymbolAddress((void**)&genc, g_enc);

    // QKV projections
    sgemm64<<<dim3(C_ / 64, M_ / 64), 256>>>(x, wq, gq, M_, C_, C_);
    sgemm64<<<dim3((KH * H_) / 64, M_ / 64), 256>>>(x, wk, gk, M_, KH * H_, C_);
    sgemm64<<<dim3((KH * H_) / 64, M_ / 64), 256>>>(x, wv, gv, M_, KH * H_, C_);

    // RMSNorm + RoPE (+ fold attention scale into q)
    const float qscale = 0.08838834764831845f;  // 1/sqrt(128)
    rmsrope_kernel<<<M_, 256>>>(gq, C_, qscale);
    rmsrope_kernel<<<M_, 256>>>(gk, KH * H_, 1.0f);

    // Attention
    attn_kernel<<<dim3(T_ / 8, NH, B_), 256>>>(gq, gk, gv, genc);

    // Output projection
    sgemm64<<<dim3(C_ / 64, M_ / 64), 256>>>(genc, wo, out, M_, C_, C_);
}

// round 3
// speedup vs baseline: 1.3284x; 1.3284x over previous
#include <cuda_runtime.h>
#include <cuda_bf16.h>
#include <math.h>
#include <stdint.h>

// Problem constants
#define B_  2
#define T_  1024
#define C_  2048
#define NH  16
#define KH  4
#define H_  128
#define M_  (B_*T_)

// Scratch
__device__ float g_q[M_ * C_];
__device__ float g_k[M_ * (KH*H_)];
__device__ float g_v[M_ * (KH*H_)];
__device__ float g_enc[M_ * C_];

// ---------------------------------------------------------------------------
// bf16x3-split tensor-core GEMM: C[M,N](fp32) = A[M,K](fp32) @ B[K,N](fp32)
// Tile 128x128x32, 512 threads (16 warps as 4x4), mma.sync.m16n8k16.bf16.
// C ≈ Ahi@Bhi + Alo@Bhi + Ahi@Blo   (lo*lo dropped, ~2^-17 rel)
// ---------------------------------------------------------------------------
__device__ __forceinline__ void ldsm_x4(uint32_t& r0, uint32_t& r1, uint32_t& r2,
                                        uint32_t& r3, uint32_t addr) {
    asm volatile("ldmatrix.sync.aligned.m8n8.x4.shared.b16 {%0,%1,%2,%3}, [%4];"
                 : "=r"(r0), "=r"(r1), "=r"(r2), "=r"(r3) : "r"(addr));
}
__device__ __forceinline__ void ldsm_x2t(uint32_t& r0, uint32_t& r1, uint32_t addr) {
    asm volatile("ldmatrix.sync.aligned.m8n8.x2.trans.shared.b16 {%0,%1}, [%2];"
                 : "=r"(r0), "=r"(r1) : "r"(addr));
}
__device__ __forceinline__ void mma16816(float* c, const uint32_t* a, const uint32_t* b) {
    asm volatile("mma.sync.aligned.m16n8k16.row.col.f32.bf16.bf16.f32 "
                 "{%0,%1,%2,%3}, {%4,%5,%6,%7}, {%8,%9}, {%0,%1,%2,%3};"
                 : "+f"(c[0]), "+f"(c[1]), "+f"(c[2]), "+f"(c[3])
                 : "r"(a[0]), "r"(a[1]), "r"(a[2]), "r"(a[3]), "r"(b[0]), "r"(b[1]));
}

__device__ __forceinline__ uint32_t pack_bf2(__nv_bfloat16 a, __nv_bfloat16 b) {
    __nv_bfloat162 t = __halves2bfloat162(a, b);
    return *reinterpret_cast<uint32_t*>(&t);
}

#define ASTRIDE 40
#define BSTRIDE 136

__device__ __forceinline__ void gemm_body(
    const float* __restrict__ A, const float* __restrict__ B, float* __restrict__ C,
    int N, int K, int bm0, int bn0)
{
    __shared__ __align__(16) __nv_bfloat16 sAhi[128][ASTRIDE];
    __shared__ __align__(16) __nv_bfloat16 sAlo[128][ASTRIDE];
    __shared__ __align__(16) __nv_bfloat16 sBhi[32][BSTRIDE];
    __shared__ __align__(16) __nv_bfloat16 sBlo[32][BSTRIDE];

    const int tid = threadIdx.x;
    const int lane = tid & 31;
    const int warp = tid >> 5;
    const int wm = (warp >> 2) * 32;
    const int wn = (warp & 3) * 32;

    float acc[2][4][4];
    #pragma unroll
    for (int i = 0; i < 2; i++)
        #pragma unroll
        for (int j = 0; j < 4; j++)
            #pragma unroll
            for (int u = 0; u < 4; u++) acc[i][j][u] = 0.f;

    const uint32_t aHiB = (uint32_t)__cvta_generic_to_shared(&sAhi[0][0]);
    const uint32_t aLoB = (uint32_t)__cvta_generic_to_shared(&sAlo[0][0]);
    const uint32_t bHiB = (uint32_t)__cvta_generic_to_shared(&sBhi[0][0]);
    const uint32_t bLoB = (uint32_t)__cvta_generic_to_shared(&sBlo[0][0]);

    // producer indices
    const int ia0 = tid, ia1 = tid + 512;       // A: 1024 float4s (128 rows x 8)
    const int arow0 = ia0 >> 3, ac0 = (ia0 & 7) << 2;
    const int arow1 = ia1 >> 3, ac1 = (ia1 & 7) << 2;
    const int brow0 = ia0 >> 5, bc0 = (ia0 & 31) << 2;   // B: 32 rows x 32 float4
    const int brow1 = ia1 >> 5, bc1 = (ia1 & 31) << 2;

    float4 pa0, pa1, pb0, pb1;
    pa0 = *(const float4*)&A[(size_t)(bm0 + arow0) * K + ac0];
    pa1 = *(const float4*)&A[(size_t)(bm0 + arow1) * K + ac1];
    pb0 = *(const float4*)&B[(size_t)brow0 * N + bn0 + bc0];
    pb1 = *(const float4*)&B[(size_t)brow1 * N + bn0 + bc1];

    for (int k0 = 0; k0 < K; k0 += 32) {
        // split+store current tile
        {
            float4 v = pa0;
            __nv_bfloat16 h0=__float2bfloat16(v.x), h1=__float2bfloat16(v.y),
                          h2=__float2bfloat16(v.z), h3=__float2bfloat16(v.w);
            uint2 uh = make_uint2(pack_bf2(h0,h1), pack_bf2(h2,h3));
            uint2 ul = make_uint2(
                pack_bf2(__float2bfloat16(v.x-__bfloat162float(h0)), __float2bfloat16(v.y-__bfloat162float(h1))),
                pack_bf2(__float2bfloat16(v.z-__bfloat162float(h2)), __float2bfloat16(v.w-__bfloat162float(h3))));
            *(uint2*)&sAhi[arow0][ac0] = uh;
            *(uint2*)&sAlo[arow0][ac0] = ul;
        }
        {
            float4 v = pa1;
            __nv_bfloat16 h0=__float2bfloat16(v.x), h1=__float2bfloat16(v.y),
                          h2=__float2bfloat16(v.z), h3=__float2bfloat16(v.w);
            uint2 uh = make_uint2(pack_bf2(h0,h1), pack_bf2(h2,h3));
            uint2 ul = make_uint2(
                pack_bf2(__float2bfloat16(v.x-__bfloat162float(h0)), __float2bfloat16(v.y-__bfloat162float(h1))),
                pack_bf2(__float2bfloat16(v.z-__bfloat162float(h2)), __float2bfloat16(v.w-__bfloat162float(h3))));
            *(uint2*)&sAhi[arow1][ac1] = uh;
            *(uint2*)&sAlo[arow1][ac1] = ul;
        }
        {
            float4 v = pb0;
            __nv_bfloat16 h0=__float2bfloat16(v.x), h1=__float2bfloat16(v.y),
                          h2=__float2bfloat16(v.z), h3=__float2bfloat16(v.w);
            uint2 uh = make_uint2(pack_bf2(h0,h1), pack_bf2(h2,h3));
            uint2 ul = make_uint2(
                pack_bf2(__float2bfloat16(v.x-__bfloat162float(h0)), __float2bfloat16(v.y-__bfloat162float(h1))),
                pack_bf2(__float2bfloat16(v.z-__bfloat162float(h2)), __float2bfloat16(v.w-__bfloat162float(h3))));
            *(uint2*)&sBhi[brow0][bc0] = uh;
            *(uint2*)&sBlo[brow0][bc0] = ul;
        }
        {
            float4 v = pb1;
            __nv_bfloat16 h0=__float2bfloat16(v.x), h1=__float2bfloat16(v.y),
                          h2=__float2bfloat16(v.z), h3=__float2bfloat16(v.w);
            uint2 uh = make_uint2(pack_bf2(h0,h1), pack_bf2(h2,h3));
            uint2 ul = make_uint2(
                pack_bf2(__float2bfloat16(v.x-__bfloat162float(h0)), __float2bfloat16(v.y-__bfloat162float(h1))),
                pack_bf2(__float2bfloat16(v.z-__bfloat162float(h2)), __float2bfloat16(v.w-__bfloat162float(h3))));
            *(uint2*)&sBhi[brow1][bc1] = uh;
            *(uint2*)&sBlo[brow1][bc1] = ul;
        }
        __syncthreads();

        // prefetch next tile
        if (k0 + 32 < K) {
            pa0 = *(const float4*)&A[(size_t)(bm0 + arow0) * K + k0 + 32 + ac0];
            pa1 = *(const float4*)&A[(size_t)(bm0 + arow1) * K + k0 + 32 + ac1];
            pb0 = *(const float4*)&B[(size_t)(k0 + 32 + brow0) * N + bn0 + bc0];
            pb1 = *(const float4*)&B[(size_t)(k0 + 32 + brow1) * N + bn0 + bc1];
        }

        // compute: 2 k16-steps
        #pragma unroll
        for (int ks = 0; ks < 32; ks += 16) {
            uint32_t ah[2][4], al[2][4], bh[4][2], bl[4][2];
            const int arow = (lane & 15);
            const int acol = ks + ((lane >> 4) << 3);
            #pragma unroll
            for (int i = 0; i < 2; i++) {
                uint32_t off = (uint32_t)((wm + i*16 + arow) * ASTRIDE + acol) * 2;
                ldsm_x4(ah[i][0], ah[i][1], ah[i][2], ah[i][3], aHiB + off);
                ldsm_x4(al[i][0], al[i][1], al[i][2], al[i][3], aLoB + off);
            }
            const int brow = ks + (lane & 15);
            #pragma unroll
            for (int j = 0; j < 4; j++) {
                uint32_t off = (uint32_t)(brow * BSTRIDE + wn + j*8) * 2;
                ldsm_x2t(bh[j][0], bh[j][1], bHiB + off);
                ldsm_x2t(bl[j][0], bl[j][1], bLoB + off);
            }
            #pragma unroll
            for (int i = 0; i < 2; i++)
                #pragma unroll
                for (int j = 0; j < 4; j++) {
                    mma16816(acc[i][j], ah[i], bh[j]);
                    mma16816(acc[i][j], al[i], bh[j]);
                    mma16816(acc[i][j], ah[i], bl[j]);
                }
        }
        __syncthreads();
    }

    // epilogue
    const int g = lane >> 2, tg = lane & 3;
    #pragma unroll
    for (int i = 0; i < 2; i++)
        #pragma unroll
        for (int j = 0; j < 4; j++) {
            int r0 = bm0 + wm + i*16 + g;
            int c0 = bn0 + wn + j*8 + tg*2;
            *(float2*)&C[(size_t)r0 * N + c0]       = make_float2(acc[i][j][0], acc[i][j][1]);
            *(float2*)&C[(size_t)(r0+8) * N + c0]   = make_float2(acc[i][j][2], acc[i][j][3]);
        }
}

__global__ __launch_bounds__(512, 1) void gemm_nn(
    const float* __restrict__ A, const float* __restrict__ B, float* __restrict__ C,
    int N, int K)
{
    gemm_body(A, B, C, N, K, blockIdx.y * 128, blockIdx.x * 128);
}

__global__ __launch_bounds__(512, 1) void gemm_kv(
    const float* __restrict__ x, const float* __restrict__ wk, const float* __restrict__ wv,
    float* __restrict__ gk, float* __restrict__ gv)
{
    const float* Bp = blockIdx.z ? wv : wk;
    float* Cp = blockIdx.z ? gv : gk;
    gemm_body(x, Bp, Cp, KH * H_, C_, blockIdx.y * 128, blockIdx.x * 128);
}

// ---------------------------------------------------------------------------
// Fused RMSNorm + RoPE (+ scale). One block per row.
// ---------------------------------------------------------------------------
__global__ void rmsrope_kernel(float* __restrict__ buf, int D, float scale) {
    __shared__ float s_x[2048];
    __shared__ float s_wred[8];

    const int row = blockIdx.x;
    const int t = row % T_;
    const int tid = threadIdx.x;
    const int lane = tid & 31;
    const int warp = tid >> 5;
    float* rp = buf + (size_t)row * D;

    float ss = 0.f;
    for (int d = tid; d < D; d += 256) {
        float v = rp[d];
        s_x[d] = v;
        ss = fmaf(v, v, ss);
    }
    #pragma unroll
    for (int off = 16; off > 0; off >>= 1)
        ss += __shfl_xor_sync(0xffffffffu, ss, off);
    if (lane == 0) s_wred[warp] = ss;
    __syncthreads();
    float tot = 0.f;
    #pragma unroll
    for (int w = 0; w < 8; w++) tot += s_wred[w];
    const float inv = rsqrtf(tot / (float)D + 1e-6f) * scale;

    for (int d = tid; d < D; d += 256) {
        int h = d & 127;
        int i = h & 63;
        float fraction = (float)i * (1.0f / 64.0f);
        float inv_freq = powf(10000.0f, -fraction);
        float ang = (float)t * inv_freq;
        float sv = sinf(ang), cv = cosf(ang);
        float xn = s_x[d] * inv;
        float partner = (h < 64) ? s_x[d + 64] : s_x[d - 64];
        partner *= inv;
        float val = (h < 64) ? fmaf(xn, cv, -partner * sv)
                             : fmaf(xn, cv,  partner * sv);
        rp[d] = val;
    }
}

// ---------------------------------------------------------------------------
// Attention (SIMT): one warp per query, online softmax, 32-key tiles.
// ---------------------------------------------------------------------------
#define ST 32
__global__ void attn_kernel(const float* __restrict__ q, const float* __restrict__ k,
                            const float* __restrict__ v, float* __restrict__ enc) {
    __shared__ float q_s[8][128];
    __shared__ float k_s[ST][129];
    __shared__ float v_s[ST][129];

    const int tid = threadIdx.x;
    const int lane = tid & 31;
    const int warp = tid >> 5;
    const int b = blockIdx.z;
    const int n = blockIdx.y;
    const int kh = n >> 2;
    const int t0 = blockIdx.x * 8;
    const int t = t0 + warp;

    {
        int qrow = tid >> 5;
        int qc = (tid & 31) << 2;
        float4 qv = *(const float4*)&q[((size_t)(b * T_ + t0 + qrow) * C_) + n * H_ + qc];
        *(float4*)&q_s[qrow][qc] = qv;
    }

    float m = -INFINITY, l = 0.f;
    float o0 = 0.f, o1 = 0.f, o2 = 0.f, o3 = 0.f;

    for (int s0 = 0; s0 < T_; s0 += ST) {
        __syncthreads();
        #pragma unroll
        for (int j = 0; j < 4; j++) {
            int i = tid + j * 256;
            int srow = i >> 5;
            int c4 = (i & 31) << 2;
            size_t goff = ((size_t)(b * T_ + s0 + srow) * (KH * H_)) + kh * H_ + c4;
            float4 kv = *(const float4*)&k[goff];
            float4 vv = *(const float4*)&v[goff];
            k_s[srow][c4 + 0] = kv.x; k_s[srow][c4 + 1] = kv.y;
            k_s[srow][c4 + 2] = kv.z; k_s[srow][c4 + 3] = kv.w;
            v_s[srow][c4 + 0] = vv.x; v_s[srow][c4 + 1] = vv.y;
            v_s[srow][c4 + 2] = vv.z; v_s[srow][c4 + 3] = vv.w;
        }
        __syncthreads();

        float lg = 0.f;
        #pragma unroll 8
        for (int h = 0; h < 128; h++)
            lg = fmaf(q_s[warp][h], k_s[lane][h], lg);

        float mx = lg;
        #pragma unroll
        for (int off = 16; off > 0; off >>= 1)
            mx = fmaxf(mx, __shfl_xor_sync(0xffffffffu, mx, off));
        float m_new = fmaxf(m, mx);
        float alpha = expf(m - m_new);
        float p = expf(lg - m_new);
        float ps = p;
        #pragma unroll
        for (int off = 16; off > 0; off >>= 1)
            ps += __shfl_xor_sync(0xffffffffu, ps, off);
        l = l * alpha + ps;
        o0 *= alpha; o1 *= alpha; o2 *= alpha; o3 *= alpha;
        m = m_new;

        #pragma unroll
        for (int sl = 0; sl < ST; sl++) {
            float pb = __shfl_sync(0xffffffffu, p, sl);
            o0 = fmaf(pb, v_s[sl][lane],       o0);
            o1 = fmaf(pb, v_s[sl][32 + lane],  o1);
            o2 = fmaf(pb, v_s[sl][64 + lane],  o2);
            o3 = fmaf(pb, v_s[sl][96 + lane],  o3);
        }
    }

    float il = 1.0f / l;
    size_t ob = ((size_t)(b * T_ + t) * C_) + n * H_;
    enc[ob + lane]       = o0 * il;
    enc[ob + 32 + lane]  = o1 * il;
    enc[ob + 64 + lane]  = o2 * il;
    enc[ob + 96 + lane]  = o3 * il;
}

// ---------------------------------------------------------------------------
extern "C" void kernel_launch(void* const* d_in, const int* in_sizes, int n_in,
                              void* d_out, int out_size) {
    const float* x  = (const float*)d_in[0];
    const float* wq = (const float*)d_in[1];
    const float* wk = (const float*)d_in[2];
    const float* wv = (const float*)d_in[3];
    const float* wo = (const float*)d_in[4];
    float* out = (float*)d_out;

    float *gq, *gk, *gv, *genc;
    cudaGetSymbolAddress((void**)&gq, g_q);
    cudaGetSymbolAddress((void**)&gk, g_k);
    cudaGetSymbolAddress((void**)&gv, g_v);
    cudaGetSymbolAddress((void**)&genc, g_enc);

    // QKV projections (tensor-core bf16x3)
    gemm_nn<<<dim3(C_ / 128, M_ / 128), 512>>>(x, wq, gq, C_, C_);
    gemm_kv<<<dim3((KH * H_) / 128, M_ / 128, 2), 512>>>(x, wk, wv, gk, gv);

    // RMSNorm + RoPE
    const float qscale = 0.08838834764831845f;  // 1/sqrt(128)
    rmsrope_kernel<<<M_, 256>>>(gq, C_, qscale);
    rmsrope_kernel<<<M_, 256>>>(gk, KH * H_, 1.0f);

    // Attention
    attn_kernel<<<dim3(T_ / 8, NH, B_), 256>>>(gq, gk, gv, genc);

    // Output projection
    gemm_nn<<<dim3(C_ / 128, M_ / 128), 512>>>(genc, wo, out, C_, C_);
}

// round 4
// speedup vs baseline: 4.6767x; 3.5205x over previous
#include <cuda_runtime.h>
#include <cuda_bf16.h>
#include <math.h>
#include <stdint.h>

#define B_  2
#define T_  1024
#define C_  2048
#define NH  16
#define KH  4
#define H_  128
#define M_  (B_*T_)

__device__ float g_q[M_ * C_];
__device__ float g_k[M_ * (KH*H_)];
__device__ float g_v[M_ * (KH*H_)];
__device__ float g_enc[M_ * C_];

// ---------------- mma / ldmatrix helpers ----------------
__device__ __forceinline__ void ldsm_x4(uint32_t& r0, uint32_t& r1, uint32_t& r2,
                                        uint32_t& r3, uint32_t addr) {
    asm volatile("ldmatrix.sync.aligned.m8n8.x4.shared.b16 {%0,%1,%2,%3}, [%4];"
                 : "=r"(r0), "=r"(r1), "=r"(r2), "=r"(r3) : "r"(addr));
}
__device__ __forceinline__ void ldsm_x2(uint32_t& r0, uint32_t& r1, uint32_t addr) {
    asm volatile("ldmatrix.sync.aligned.m8n8.x2.shared.b16 {%0,%1}, [%2];"
                 : "=r"(r0), "=r"(r1) : "r"(addr));
}
__device__ __forceinline__ void ldsm_x2t(uint32_t& r0, uint32_t& r1, uint32_t addr) {
    asm volatile("ldmatrix.sync.aligned.m8n8.x2.trans.shared.b16 {%0,%1}, [%2];"
                 : "=r"(r0), "=r"(r1) : "r"(addr));
}
__device__ __forceinline__ void mma16816(float* c, const uint32_t* a, const uint32_t* b) {
    asm volatile("mma.sync.aligned.m16n8k16.row.col.f32.bf16.bf16.f32 "
                 "{%0,%1,%2,%3}, {%4,%5,%6,%7}, {%8,%9}, {%0,%1,%2,%3};"
                 : "+f"(c[0]), "+f"(c[1]), "+f"(c[2]), "+f"(c[3])
                 : "r"(a[0]), "r"(a[1]), "r"(a[2]), "r"(a[3]), "r"(b[0]), "r"(b[1]));
}
__device__ __forceinline__ uint32_t pack_bf2(__nv_bfloat16 a, __nv_bfloat16 b) {
    __nv_bfloat162 t = __halves2bfloat162(a, b);
    return *reinterpret_cast<uint32_t*>(&t);
}
__device__ __forceinline__ uint32_t pack_hi2(float x, float y) {
    return pack_bf2(__float2bfloat16(x), __float2bfloat16(y));
}
__device__ __forceinline__ uint32_t pack_lo2(float x, float y) {
    __nv_bfloat16 hx = __float2bfloat16(x), hy = __float2bfloat16(y);
    return pack_bf2(__float2bfloat16(x - __bfloat162float(hx)),
                    __float2bfloat16(y - __bfloat162float(hy)));
}
// split a float4 into hi/lo bf16x2 pairs and store (8 bytes each)
__device__ __forceinline__ void split_store(float4 v, __nv_bfloat16* hi, __nv_bfloat16* lo) {
    *(uint2*)hi = make_uint2(pack_hi2(v.x, v.y), pack_hi2(v.z, v.w));
    *(uint2*)lo = make_uint2(pack_lo2(v.x, v.y), pack_lo2(v.z, v.w));
}

// ---------------------------------------------------------------------------
// bf16x3-split tensor-core GEMM (unchanged from R3)
// ---------------------------------------------------------------------------
#define ASTRIDE 40
#define BSTRIDE 136

__device__ __forceinline__ void gemm_body(
    const float* __restrict__ A, const float* __restrict__ B, float* __restrict__ C,
    int N, int K, int bm0, int bn0)
{
    __shared__ __align__(16) __nv_bfloat16 sAhi[128][ASTRIDE];
    __shared__ __align__(16) __nv_bfloat16 sAlo[128][ASTRIDE];
    __shared__ __align__(16) __nv_bfloat16 sBhi[32][BSTRIDE];
    __shared__ __align__(16) __nv_bfloat16 sBlo[32][BSTRIDE];

    const int tid = threadIdx.x;
    const int lane = tid & 31;
    const int warp = tid >> 5;
    const int wm = (warp >> 2) * 32;
    const int wn = (warp & 3) * 32;

    float acc[2][4][4];
    #pragma unroll
    for (int i = 0; i < 2; i++)
        #pragma unroll
        for (int j = 0; j < 4; j++)
            #pragma unroll
            for (int u = 0; u < 4; u++) acc[i][j][u] = 0.f;

    const uint32_t aHiB = (uint32_t)__cvta_generic_to_shared(&sAhi[0][0]);
    const uint32_t aLoB = (uint32_t)__cvta_generic_to_shared(&sAlo[0][0]);
    const uint32_t bHiB = (uint32_t)__cvta_generic_to_shared(&sBhi[0][0]);
    const uint32_t bLoB = (uint32_t)__cvta_generic_to_shared(&sBlo[0][0]);

    const int ia0 = tid, ia1 = tid + 512;
    const int arow0 = ia0 >> 3, ac0 = (ia0 & 7) << 2;
    const int arow1 = ia1 >> 3, ac1 = (ia1 & 7) << 2;
    const int brow0 = ia0 >> 5, bc0 = (ia0 & 31) << 2;
    const int brow1 = ia1 >> 5, bc1 = (ia1 & 31) << 2;

    float4 pa0, pa1, pb0, pb1;
    pa0 = *(const float4*)&A[(size_t)(bm0 + arow0) * K + ac0];
    pa1 = *(const float4*)&A[(size_t)(bm0 + arow1) * K + ac1];
    pb0 = *(const float4*)&B[(size_t)brow0 * N + bn0 + bc0];
    pb1 = *(const float4*)&B[(size_t)brow1 * N + bn0 + bc1];

    for (int k0 = 0; k0 < K; k0 += 32) {
        split_store(pa0, &sAhi[arow0][ac0], &sAlo[arow0][ac0]);
        split_store(pa1, &sAhi[arow1][ac1], &sAlo[arow1][ac1]);
        split_store(pb0, &sBhi[brow0][bc0], &sBlo[brow0][bc0]);
        split_store(pb1, &sBhi[brow1][bc1], &sBlo[brow1][bc1]);
        __syncthreads();

        if (k0 + 32 < K) {
            pa0 = *(const float4*)&A[(size_t)(bm0 + arow0) * K + k0 + 32 + ac0];
            pa1 = *(const float4*)&A[(size_t)(bm0 + arow1) * K + k0 + 32 + ac1];
            pb0 = *(const float4*)&B[(size_t)(k0 + 32 + brow0) * N + bn0 + bc0];
            pb1 = *(const float4*)&B[(size_t)(k0 + 32 + brow1) * N + bn0 + bc1];
        }

        #pragma unroll
        for (int ks = 0; ks < 32; ks += 16) {
            uint32_t ah[2][4], al[2][4], bh[4][2], bl[4][2];
            const int arow = (lane & 15);
            const int acol = ks + ((lane >> 4) << 3);
            #pragma unroll
            for (int i = 0; i < 2; i++) {
                uint32_t off = (uint32_t)((wm + i*16 + arow) * ASTRIDE + acol) * 2;
                ldsm_x4(ah[i][0], ah[i][1], ah[i][2], ah[i][3], aHiB + off);
                ldsm_x4(al[i][0], al[i][1], al[i][2], al[i][3], aLoB + off);
            }
            const int brow = ks + (lane & 15);
            #pragma unroll
            for (int j = 0; j < 4; j++) {
                uint32_t off = (uint32_t)(brow * BSTRIDE + wn + j*8) * 2;
                ldsm_x2t(bh[j][0], bh[j][1], bHiB + off);
                ldsm_x2t(bl[j][0], bl[j][1], bLoB + off);
            }
            #pragma unroll
            for (int i = 0; i < 2; i++)
                #pragma unroll
                for (int j = 0; j < 4; j++) {
                    mma16816(acc[i][j], ah[i], bh[j]);
                    mma16816(acc[i][j], al[i], bh[j]);
                    mma16816(acc[i][j], ah[i], bl[j]);
                }
        }
        __syncthreads();
    }

    const int g = lane >> 2, tg = lane & 3;
    #pragma unroll
    for (int i = 0; i < 2; i++)
        #pragma unroll
        for (int j = 0; j < 4; j++) {
            int r0 = bm0 + wm + i*16 + g;
            int c0 = bn0 + wn + j*8 + tg*2;
            *(float2*)&C[(size_t)r0 * N + c0]       = make_float2(acc[i][j][0], acc[i][j][1]);
            *(float2*)&C[(size_t)(r0+8) * N + c0]   = make_float2(acc[i][j][2], acc[i][j][3]);
        }
}

__global__ __launch_bounds__(512, 1) void gemm_nn(
    const float* __restrict__ A, const float* __restrict__ B, float* __restrict__ C,
    int N, int K)
{
    gemm_body(A, B, C, N, K, blockIdx.y * 128, blockIdx.x * 128);
}

__global__ __launch_bounds__(512, 1) void gemm_kv(
    const float* __restrict__ x, const float* __restrict__ wk, const float* __restrict__ wv,
    float* __restrict__ gk, float* __restrict__ gv)
{
    const float* Bp = blockIdx.z ? wv : wk;
    float* Cp = blockIdx.z ? gv : gk;
    gemm_body(x, Bp, Cp, KH * H_, C_, blockIdx.y * 128, blockIdx.x * 128);
}

// ---------------------------------------------------------------------------
// Fused RMSNorm + RoPE (+ scale). One block per row.
// ---------------------------------------------------------------------------
__global__ void rmsrope_kernel(float* __restrict__ buf, int D, float scale) {
    __shared__ float s_x[2048];
    __shared__ float s_wred[8];

    const int row = blockIdx.x;
    const int t = row % T_;
    const int tid = threadIdx.x;
    const int lane = tid & 31;
    const int warp = tid >> 5;
    float* rp = buf + (size_t)row * D;

    float ss = 0.f;
    for (int d = tid; d < D; d += 256) {
        float v = rp[d];
        s_x[d] = v;
        ss = fmaf(v, v, ss);
    }
    #pragma unroll
    for (int off = 16; off > 0; off >>= 1)
        ss += __shfl_xor_sync(0xffffffffu, ss, off);
    if (lane == 0) s_wred[warp] = ss;
    __syncthreads();
    float tot = 0.f;
    #pragma unroll
    for (int w = 0; w < 8; w++) tot += s_wred[w];
    const float inv = rsqrtf(tot / (float)D + 1e-6f) * scale;

    for (int d = tid; d < D; d += 256) {
        int h = d & 127;
        int i = h & 63;
        float fraction = (float)i * (1.0f / 64.0f);
        float inv_freq = powf(10000.0f, -fraction);
        float ang = (float)t * inv_freq;
        float sv = sinf(ang), cv = cosf(ang);
        float xn = s_x[d] * inv;
        float partner = (h < 64) ? s_x[d + 64] : s_x[d - 64];
        partner *= inv;
        float val = (h < 64) ? fmaf(xn, cv, -partner * sv)
                             : fmaf(xn, cv,  partner * sv);
        rp[d] = val;
    }
}

// ---------------------------------------------------------------------------
// Tensor-core flash attention. Block = (128-query tile, head, batch),
// 256 threads / 8 warps; warp owns 16 query rows. 64-key tiles, bf16x3.
// ---------------------------------------------------------------------------
#define BQ 128
#define BK 64
#define QS 136   // bf16 stride per row

#define SQH 0
#define SQL (BQ*QS)            // 17408
#define SKH (2*BQ*QS)          // 34816
#define SKL (SKH + BK*QS)      // 43520
#define SVH (SKL + BK*QS)      // 52224
#define SVL (SVH + BK*QS)      // 60928
#define SM_ELEMS (SVL + BK*QS) // 69632
#define ATTN_SMEM (SM_ELEMS * 2)

__global__ __launch_bounds__(256, 1) void attn_mma(
    const float* __restrict__ q, const float* __restrict__ k,
    const float* __restrict__ v, float* __restrict__ enc)
{
    extern __shared__ __nv_bfloat16 sm[];
    const int tid = threadIdx.x;
    const int lane = tid & 31;
    const int warp = tid >> 5;
    const int b = blockIdx.z;
    const int n = blockIdx.y;
    const int kh = n >> 2;
    const int t0 = blockIdx.x * BQ;

    const uint32_t smB = (uint32_t)__cvta_generic_to_shared(sm);

    // ---- load + split Q tile (128x128) ----
    #pragma unroll
    for (int j = 0; j < 16; j++) {
        int i = tid + j * 256;
        int row = i >> 5, c4 = (i & 31) << 2;
        float4 vq = *(const float4*)&q[((size_t)(b * T_ + t0 + row) * C_) + n * H_ + c4];
        split_store(vq, &sm[SQH + row * QS + c4], &sm[SQL + row * QS + c4]);
    }

    const int g = lane >> 2, tg = lane & 3;
    float m0 = -INFINITY, m1 = -INFINITY, l0 = 0.f, l1 = 0.f;
    float o[16][4];
    #pragma unroll
    for (int nn = 0; nn < 16; nn++)
        #pragma unroll
        for (int u = 0; u < 4; u++) o[nn][u] = 0.f;

    for (int s0 = 0; s0 < T_; s0 += BK) {
        __syncthreads();
        // ---- load + split K,V tiles (64x128 each) ----
        #pragma unroll
        for (int j = 0; j < 8; j++) {
            int i = tid + j * 256;
            int row = i >> 5, c4 = (i & 31) << 2;
            size_t goff = ((size_t)(b * T_ + s0 + row) * (KH * H_)) + kh * H_ + c4;
            float4 kv = *(const float4*)&k[goff];
            float4 vv = *(const float4*)&v[goff];
            split_store(kv, &sm[SKH + row * QS + c4], &sm[SKL + row * QS + c4]);
            split_store(vv, &sm[SVH + row * QS + c4], &sm[SVL + row * QS + c4]);
        }
        __syncthreads();

        // ---- S = Q @ K^T  (m16 x n64) ----
        float s[8][4];
        #pragma unroll
        for (int j = 0; j < 8; j++)
            #pragma unroll
            for (int u = 0; u < 4; u++) s[j][u] = 0.f;

        #pragma unroll
        for (int ks = 0; ks < 8; ks++) {
            uint32_t qh[4], ql[4];
            uint32_t qoff = (uint32_t)((warp * 16 + (lane & 15)) * QS
                                       + ks * 16 + ((lane >> 4) << 3)) * 2;
            ldsm_x4(qh[0], qh[1], qh[2], qh[3], smB + (SQH * 2) + qoff);
            ldsm_x4(ql[0], ql[1], ql[2], ql[3], smB + (SQL * 2) + qoff);
            #pragma unroll
            for (int j = 0; j < 8; j++) {
                uint32_t kh2[2], kl2[2];
                uint32_t koff = (uint32_t)((j * 8 + (lane & 7)) * QS
                                           + ks * 16 + (((lane & 15) >> 3) << 3)) * 2;
                ldsm_x2(kh2[0], kh2[1], smB + (SKH * 2) + koff);
                ldsm_x2(kl2[0], kl2[1], smB + (SKL * 2) + koff);
                mma16816(s[j], qh, kh2);
                mma16816(s[j], ql, kh2);
                mma16816(s[j], qh, kl2);
            }
        }

        // ---- online softmax on fragment ----
        float mx0 = -INFINITY, mx1 = -INFINITY;
        #pragma unroll
        for (int j = 0; j < 8; j++) {
            mx0 = fmaxf(mx0, fmaxf(s[j][0], s[j][1]));
            mx1 = fmaxf(mx1, fmaxf(s[j][2], s[j][3]));
        }
        mx0 = fmaxf(mx0, __shfl_xor_sync(0xffffffffu, mx0, 1));
        mx0 = fmaxf(mx0, __shfl_xor_sync(0xffffffffu, mx0, 2));
        mx1 = fmaxf(mx1, __shfl_xor_sync(0xffffffffu, mx1, 1));
        mx1 = fmaxf(mx1, __shfl_xor_sync(0xffffffffu, mx1, 2));
        float m0n = fmaxf(m0, mx0);
        float m1n = fmaxf(m1, mx1);
        float a0 = __expf(m0 - m0n);
        float a1 = __expf(m1 - m1n);
        float sum0 = 0.f, sum1 = 0.f;
        #pragma unroll
        for (int j = 0; j < 8; j++) {
            s[j][0] = __expf(s[j][0] - m0n);
            s[j][1] = __expf(s[j][1] - m0n);
            s[j][2] = __expf(s[j][2] - m1n);
            s[j][3] = __expf(s[j][3] - m1n);
            sum0 += s[j][0] + s[j][1];
            sum1 += s[j][2] + s[j][3];
        }
        sum0 += __shfl_xor_sync(0xffffffffu, sum0, 1);
        sum0 += __shfl_xor_sync(0xffffffffu, sum0, 2);
        sum1 += __shfl_xor_sync(0xffffffffu, sum1, 1);
        sum1 += __shfl_xor_sync(0xffffffffu, sum1, 2);
        l0 = l0 * a0 + sum0;
        l1 = l1 * a1 + sum1;
        m0 = m0n; m1 = m1n;
        #pragma unroll
        for (int nn = 0; nn < 16; nn++) {
            o[nn][0] *= a0; o[nn][1] *= a0;
            o[nn][2] *= a1; o[nn][3] *= a1;
        }

        // ---- O += P @ V ----
        #pragma unroll
        for (int kk = 0; kk < 4; kk++) {
            const int j0 = kk * 2;
            uint32_t ah[4], al[4];
            ah[0] = pack_hi2(s[j0][0],   s[j0][1]);
            ah[1] = pack_hi2(s[j0][2],   s[j0][3]);
            ah[2] = pack_hi2(s[j0+1][0], s[j0+1][1]);
            ah[3] = pack_hi2(s[j0+1][2], s[j0+1][3]);
            al[0] = pack_lo2(s[j0][0],   s[j0][1]);
            al[1] = pack_lo2(s[j0][2],   s[j0][3]);
            al[2] = pack_lo2(s[j0+1][0], s[j0+1][1]);
            al[3] = pack_lo2(s[j0+1][2], s[j0+1][3]);
            #pragma unroll
            for (int nn = 0; nn < 16; nn++) {
                uint32_t bh2[2], bl2[2];
                uint32_t voff = (uint32_t)((kk * 16 + (lane & 15)) * QS + nn * 8) * 2;
                ldsm_x2t(bh2[0], bh2[1], smB + (SVH * 2) + voff);
                ldsm_x2t(bl2[0], bl2[1], smB + (SVL * 2) + voff);
                mma16816(o[nn], ah, bh2);
                mma16816(o[nn], al, bh2);
                mma16816(o[nn], ah, bl2);
            }
        }
    }

    // ---- epilogue: normalize and write ----
    float il0 = 1.0f / l0;
    float il1 = 1.0f / l1;
    const int r0 = t0 + warp * 16 + g;
    #pragma unroll
    for (int nn = 0; nn < 16; nn++) {
        int c0 = nn * 8 + tg * 2;
        size_t base0 = ((size_t)(b * T_ + r0) * C_) + n * H_ + c0;
        size_t base1 = ((size_t)(b * T_ + r0 + 8) * C_) + n * H_ + c0;
        *(float2*)&enc[base0] = make_float2(o[nn][0] * il0, o[nn][1] * il0);
        *(float2*)&enc[base1] = make_float2(o[nn][2] * il1, o[nn][3] * il1);
    }
}

// ---------------------------------------------------------------------------
extern "C" void kernel_launch(void* const* d_in, const int* in_sizes, int n_in,
                              void* d_out, int out_size) {
    const float* x  = (const float*)d_in[0];
    const float* wq = (const float*)d_in[1];
    const float* wk = (const float*)d_in[2];
    const float* wv = (const float*)d_in[3];
    const float* wo = (const float*)d_in[4];
    float* out = (float*)d_out;

    float *gq, *gk, *gv, *genc;
    cudaGetSymbolAddress((void**)&gq, g_q);
    cudaGetSymbolAddress((void**)&gk, g_k);
    cudaGetSymbolAddress((void**)&gv, g_v);
    cudaGetSymbolAddress((void**)&genc, g_enc);

    static int smem_set = 0;
    if (!smem_set) {
        cudaFuncSetAttribute(attn_mma, cudaFuncAttributeMaxDynamicSharedMemorySize, ATTN_SMEM);
        smem_set = 1;
    }

    // QKV projections (tensor-core bf16x3)
    gemm_nn<<<dim3(C_ / 128, M_ / 128), 512>>>(x, wq, gq, C_, C_);
    gemm_kv<<<dim3((KH * H_) / 128, M_ / 128, 2), 512>>>(x, wk, wv, gk, gv);

    // RMSNorm + RoPE (q gets 1/sqrt(H) folded in)
    const float qscale = 0.08838834764831845f;
    rmsrope_kernel<<<M_, 256>>>(gq, C_, qscale);
    rmsrope_kernel<<<M_, 256>>>(gk, KH * H_, 1.0f);

    // Flash attention (tensor cores)
    attn_mma<<<dim3(T_ / BQ, NH, B_), 256, ATTN_SMEM>>>(gq, gk, gv, genc);

    // Output projection
    gemm_nn<<<dim3(C_ / 128, M_ / 128), 512>>>(genc, wo, out, C_, C_);
}